// round 16
// baseline (speedup 1.0000x reference)
#include <cuda_runtime.h>
#include <cstdint>
#include <cstddef>

#define Nn 8192
#define Kk 64
#define RR 64                  // base top-R per spark row (sorted desc)
#define HASHSZ 4096
#define LISTCAP 2432
#define NREC (Kk * 36)
#define NWORK 147              // worker CTAs (stream pool)
#define GRIDSZ (1 + NWORK)
#define TILER 2                // rows per work item
#define TILEB (TILER * Nn * 4) // 64KB tile
#define NSLOT 3                // ring slots (2 tiles in flight)
// worker view of dynamic smem: NSLOT tile buffers + mbars + rowbuf
#define WB_MBAR (NSLOT * TILEB)           // 196608
#define WB_ROWS (WB_MBAR + NSLOT * 8)
#define SMEMSZ  (WB_ROWS + 64)

// ---------------------------------------------------------------------------
// device globals (counters reset at end of each run for graph replay)
// ---------------------------------------------------------------------------
__device__ unsigned long long g_top[Kk][RR];
__device__ float g_sspark[Kk];
__device__ int g_spark_done;
__device__ int g_gemv_done;
__device__ int g_row_ctr;

__device__ __forceinline__ unsigned valkey(float v) {
    return ((v > 0.f) ? __float_as_uint(v) : 0u) + 1u;
}
__device__ __forceinline__ unsigned long long pack64(unsigned key, int col) {
    return ((unsigned long long)key << 32) | (unsigned)(~(unsigned)col);
}
__device__ __forceinline__ int key_idx(unsigned long long k) {
    return (int)(~(unsigned)k);
}
__device__ __forceinline__ unsigned hash_h(unsigned key) {
    return (key * 2654435761u) & (HASHSZ - 1);
}
__device__ __forceinline__ unsigned smem_u32(const void* p) {
    return (unsigned)__cvta_generic_to_shared(p);
}
__device__ __forceinline__ void cp_async4(void* smem_dst, const void* gptr) {
    unsigned a = smem_u32(smem_dst);
    asm volatile("cp.async.ca.shared.global [%0], [%1], 4;" :: "r"(a), "l"(gptr) : "memory");
}
__device__ __forceinline__ void mbar_init_(unsigned a, unsigned cnt) {
    asm volatile("mbarrier.init.shared.b64 [%0], %1;" :: "r"(a), "r"(cnt) : "memory");
}
__device__ __forceinline__ void mbar_expect_tx_(unsigned a, unsigned bytes) {
    asm volatile("mbarrier.arrive.expect_tx.shared.b64 _, [%0], %1;" :: "r"(a), "r"(bytes) : "memory");
}
__device__ __forceinline__ void mbar_wait_(unsigned a, unsigned parity) {
    asm volatile(
        "{\n\t.reg .pred P;\n"
        "LWAIT%=:\n\t"
        "mbarrier.try_wait.parity.shared.b64 P, [%0], %1;\n\t"
        "@!P bra LWAIT%=;\n\t}"
        :: "r"(a), "r"(parity) : "memory");
}
__device__ __forceinline__ void bulk_g2s_(unsigned dst, const void* src, unsigned bytes, unsigned mbar) {
    asm volatile(
        "cp.async.bulk.shared::cluster.global.mbarrier::complete_tx::bytes [%0], [%1], %2, [%3];"
        :: "r"(dst), "l"(src), "r"(bytes), "r"(mbar) : "memory");
}
__device__ __forceinline__ void bulk_s2g_(void* gdst, unsigned ssrc, unsigned bytes) {
    asm volatile(
        "cp.async.bulk.global.shared::cta.bulk_group [%0], [%1], %2;"
        :: "l"(gdst), "r"(ssrc), "r"(bytes) : "memory");
}

// ---------------------------------------------------------------------------
// Scan shared memory (scan CTA view of the dynamic smem)
// ---------------------------------------------------------------------------
struct alignas(16) SS {
    unsigned long long top[Kk][RR];       // 32KB sorted base top lists
    unsigned long long rec[NREC];         // 18KB ordered additive records
    unsigned char rowT[Nn];               // 8KB  row-touched map
    unsigned hkey[HASHSZ];                // 16KB (epilogue accumulation)
    float    hval[HASHSZ];                // 16KB
    unsigned list[LISTCAP];               // 9.5KB distinct elements
    unsigned long long scr[64];
    unsigned long long scr2[64];
    float spec[Kk][32];                   // upfront hebbian-base prefetch
    float specR[Kk];
    float s_spark[Kk];
    unsigned char row2b[Nn];              // 8KB row -> spark bucket (255=none)
    int   spp[Kk]; float sen[Kk]; int srnd[Kk];
    int   next_all[Kk];
    int   list_cnt;
};

// epilogue-only atomic accumulate (parallel, commutative adds)
__device__ void hadd_ep(SS* sm, unsigned key, float d) {
    unsigned h = hash_h(key);
    while (true) {
        unsigned k = sm->hkey[h];
        if (k == 0xFFFFFFFFu) {
            unsigned old = atomicCAS(&sm->hkey[h], 0xFFFFFFFFu, key);
            if (old == 0xFFFFFFFFu) {
                atomicAdd(&sm->hval[h], d);
                int li = atomicAdd(&sm->list_cnt, 1);
                sm->list[li] = h;
                return;
            }
            k = old;
        }
        if (k == key) { atomicAdd(&sm->hval[h], d); return; }
        h = (h + 1) & (HASHSZ - 1);
    }
}

// ---------------------------------------------------------------------------
// ONE fused kernel, one wave (148 CTAs):
//   CTA 0        : sequential spark scan (record-based, hash-free loop)
//   CTA 1..64    : spark row top-64 + sigmoid, then join bulk-stream queue
//   CTA 65..147  : bulk-stream queue immediately (3-slot ring of 64KB tiles)
// ---------------------------------------------------------------------------
__global__ void __launch_bounds__(1024, 1) fused_kernel(
    const float* __restrict__ W,
    const float* __restrict__ s_in,
    const float* __restrict__ noise,
    const float* __restrict__ energy,
    const int*   __restrict__ spark_pos,
    const int*   __restrict__ spark_age,
    const int*   __restrict__ randint_vals,
    const int*   __restrict__ step_ptr,
    float*       __restrict__ out)
{
    __shared__ unsigned long long wl[32][RR];
    __shared__ float red[32];
    __shared__ float red2[32];

    extern __shared__ unsigned char smraw[];

    const int tid  = threadIdx.x;
    const int lane = tid & 31;
    const int wid  = tid >> 5;
    const int bid  = blockIdx.x;

    const size_t oS = Kk;
    const size_t oW = (size_t)Kk + Nn;
    const size_t oE = oW + (size_t)Nn * Nn;
    const size_t oA = oE + Kk;

    // ======================= worker CTAs =======================
    if (bid >= 1) {
        unsigned sbase = smem_u32(smraw);
        float4* fbuf = reinterpret_cast<float4*>(smraw);
        int* rowbuf  = reinterpret_cast<int*>(smraw + WB_ROWS);

        if (tid == 0) {
            #pragma unroll
            for (int q = 0; q < NSLOT; ++q)
                mbar_init_(sbase + WB_MBAR + q * 8, 1);
            asm volatile("fence.proxy.async.shared::cta;" ::: "memory");
        }
        __syncthreads();

        // ---- spark prep (CTAs 1..Kk only) ----
        if (bid <= Kk) {
            const int b   = bid - 1;
            const int row = spark_pos[b];
            const float4* r4 = reinterpret_cast<const float4*>(W + (size_t)row * Nn);
            {
                const int cbase = (wid << 8) + (lane << 3);
                float4 a = __ldg(&r4[cbase >> 2]);
                float4 c = __ldg(&r4[(cbase >> 2) + 1]);
                unsigned k0 = valkey(a.x), k1 = valkey(a.y), k2 = valkey(a.z), k3 = valkey(a.w);
                unsigned k4 = valkey(c.x), k5 = valkey(c.y), k6 = valkey(c.z), k7 = valkey(c.w);
                for (int p = 0; p < RR; ++p) {
                    unsigned bk = k0; int bj = 0;
                    if (k1 > bk) { bk = k1; bj = 1; }
                    if (k2 > bk) { bk = k2; bj = 2; }
                    if (k3 > bk) { bk = k3; bj = 3; }
                    if (k4 > bk) { bk = k4; bj = 4; }
                    if (k5 > bk) { bk = k5; bj = 5; }
                    if (k6 > bk) { bk = k6; bj = 6; }
                    if (k7 > bk) { bk = k7; bj = 7; }
                    unsigned kmax = __reduce_max_sync(0xFFFFFFFFu, bk);
                    unsigned cnd = (bk == kmax) ? (unsigned)(cbase + bj) : 0xFFFFFFFFu;
                    unsigned cmin = __reduce_min_sync(0xFFFFFFFFu, cnd);
                    if (lane == 0) wl[wid][p] = pack64(kmax, (int)cmin);
                    int rel = (int)cmin - cbase;
                    if (rel >= 0 && rel < 8) {
                        if (rel == 0) k0 = 0; if (rel == 1) k1 = 0;
                        if (rel == 2) k2 = 0; if (rel == 3) k3 = 0;
                        if (rel == 4) k4 = 0; if (rel == 5) k5 = 0;
                        if (rel == 6) k6 = 0; if (rel == 7) k7 = 0;
                    }
                }
                __syncthreads();
                if (wid == 0) {
                    int head = 0;
                    for (int p = 0; p < RR; ++p) {
                        unsigned long long cur = (head < RR) ? wl[lane][head] : 0ull;
                        unsigned hi = (unsigned)(cur >> 32);
                        unsigned kmax = __reduce_max_sync(0xFFFFFFFFu, hi);
                        unsigned lo = (hi == kmax) ? (unsigned)cur : 0u;
                        unsigned lomax = __reduce_max_sync(0xFFFFFFFFu, lo);
                        if (hi == kmax && (unsigned)cur == lomax) head++;
                        if (lane == 0)
                            g_top[b][p] = ((unsigned long long)kmax << 32) | lomax;
                    }
                }
            }
            {
                const float4* s4 = reinterpret_cast<const float4*>(s_in);
                float4 w1 = __ldg(&r4[2 * tid]),     w2 = __ldg(&r4[2 * tid + 1]);
                float4 v1 = __ldg(&s4[2 * tid]),     v2 = __ldg(&s4[2 * tid + 1]);
                float acc = w1.x * (v1.x * 0.95f) + w1.y * (v1.y * 0.95f)
                          + w1.z * (v1.z * 0.95f) + w1.w * (v1.w * 0.95f)
                          + w2.x * (v2.x * 0.95f) + w2.y * (v2.y * 0.95f)
                          + w2.z * (v2.z * 0.95f) + w2.w * (v2.w * 0.95f);
                #pragma unroll
                for (int off = 16; off; off >>= 1)
                    acc += __shfl_xor_sync(0xFFFFFFFFu, acc, off);
                if (lane == 0) red[wid] = acc;
                __syncthreads();
                if (wid == 0) {
                    float v = red[lane];
                    #pragma unroll
                    for (int off = 16; off; off >>= 1)
                        v += __shfl_xor_sync(0xFFFFFFFFu, v, off);
                    if (lane == 0) {
                        float z = v + 0.05f * noise[row];
                        g_sspark[b] = 1.0f / (1.0f + expf(-z));
                        __threadfence();
                        atomicAdd(&g_spark_done, 1);
                    }
                }
            }
            __syncthreads();
        }

        // ---- bulk-stream queue: 3-slot ring of 64KB (2-row) tiles ----
        {
            const float4* s4 = reinterpret_cast<const float4*>(s_in);
            float4 sv0 = __ldg(&s4[2 * tid]);
            float4 sv1 = __ldg(&s4[2 * tid + 1]);
            sv0.x *= 0.95f; sv0.y *= 0.95f; sv0.z *= 0.95f; sv0.w *= 0.95f;
            sv1.x *= 0.95f; sv1.y *= 0.95f; sv1.z *= 0.95f; sv1.w *= 0.95f;

            // prologue: grab two tiles, issue loads into slots 0..1
            if (tid == 0) {
                #pragma unroll
                for (int q = 0; q < 2; ++q) {
                    int r0 = atomicAdd(&g_row_ctr, TILER);
                    rowbuf[q] = r0;
                    if (r0 < Nn) {
                        mbar_expect_tx_(sbase + WB_MBAR + q * 8, TILEB);
                        bulk_g2s_(sbase + q * TILEB, W + (size_t)r0 * Nn, TILEB,
                                  sbase + WB_MBAR + q * 8);
                    }
                }
                rowbuf[2] = Nn + 1;
            }
            __syncthreads();

            for (int i = 0;; ++i) {
                const int a = i % NSLOT;
                const int row = rowbuf[a];
                if (row >= Nn) break;

                float nz = 0.f;
                if (lane == 0) {
                    if (wid == 0) nz = __ldg(&noise[row]);       // overlaps wait
                    if (wid == 1) nz = __ldg(&noise[row + 1]);
                }

                mbar_wait_(sbase + WB_MBAR + a * 8, (unsigned)((i / NSLOT) & 1));

                float4* bp = fbuf + a * 4096;      // 4096 float4 per 64KB slot
                float4 w1 = bp[2 * tid];
                float4 w2 = bp[2 * tid + 1];
                float4 w3 = bp[4096 / 2 + 2 * tid];
                float4 w4 = bp[4096 / 2 + 2 * tid + 1];
                float acc0 = w1.x * sv0.x + w1.y * sv0.y + w1.z * sv0.z + w1.w * sv0.w
                           + w2.x * sv1.x + w2.y * sv1.y + w2.z * sv1.z + w2.w * sv1.w;
                float acc1 = w3.x * sv0.x + w3.y * sv0.y + w3.z * sv0.z + w3.w * sv0.w
                           + w4.x * sv1.x + w4.y * sv1.y + w4.z * sv1.z + w4.w * sv1.w;
                float4 o;
                o.x = fminf(fmaxf(w1.x * 0.999f, -2.f), 2.f);
                o.y = fminf(fmaxf(w1.y * 0.999f, -2.f), 2.f);
                o.z = fminf(fmaxf(w1.z * 0.999f, -2.f), 2.f);
                o.w = fminf(fmaxf(w1.w * 0.999f, -2.f), 2.f);
                bp[2 * tid] = o;
                o.x = fminf(fmaxf(w2.x * 0.999f, -2.f), 2.f);
                o.y = fminf(fmaxf(w2.y * 0.999f, -2.f), 2.f);
                o.z = fminf(fmaxf(w2.z * 0.999f, -2.f), 2.f);
                o.w = fminf(fmaxf(w2.w * 0.999f, -2.f), 2.f);
                bp[2 * tid + 1] = o;
                o.x = fminf(fmaxf(w3.x * 0.999f, -2.f), 2.f);
                o.y = fminf(fmaxf(w3.y * 0.999f, -2.f), 2.f);
                o.z = fminf(fmaxf(w3.z * 0.999f, -2.f), 2.f);
                o.w = fminf(fmaxf(w3.w * 0.999f, -2.f), 2.f);
                bp[4096 / 2 + 2 * tid] = o;
                o.x = fminf(fmaxf(w4.x * 0.999f, -2.f), 2.f);
                o.y = fminf(fmaxf(w4.y * 0.999f, -2.f), 2.f);
                o.z = fminf(fmaxf(w4.z * 0.999f, -2.f), 2.f);
                o.w = fminf(fmaxf(w4.w * 0.999f, -2.f), 2.f);
                bp[4096 / 2 + 2 * tid + 1] = o;

                #pragma unroll
                for (int off = 16; off; off >>= 1) {
                    acc0 += __shfl_xor_sync(0xFFFFFFFFu, acc0, off);
                    acc1 += __shfl_xor_sync(0xFFFFFFFFu, acc1, off);
                }
                if (lane == 0) { red[wid] = acc0; red2[wid] = acc1; }
                __syncthreads();                   // smem writes + reds done

                if (wid == 1) {                    // row+1 sigmoid (parallel)
                    float v = red2[lane];
                    #pragma unroll
                    for (int off = 16; off; off >>= 1)
                        v += __shfl_xor_sync(0xFFFFFFFFu, v, off);
                    if (lane == 0) {
                        float z = v + 0.05f * nz;
                        out[oS + row + 1] = 1.0f / (1.0f + expf(-z));
                    }
                }
                if (wid == 0) {
                    float v = red[lane];
                    #pragma unroll
                    for (int off = 16; off; off >>= 1)
                        v += __shfl_xor_sync(0xFFFFFFFFu, v, off);
                    if (lane == 0) {
                        float z = v + 0.05f * nz;
                        out[oS + row] = 1.0f / (1.0f + expf(-z));
                        asm volatile("fence.proxy.async.shared::cta;" ::: "memory");
                        bulk_s2g_(out + oW + (size_t)row * Nn, sbase + a * TILEB, TILEB);
                        asm volatile("cp.async.bulk.commit_group;" ::: "memory");
                        // slot (i+2)%3 stored at iter i-1; allow 1 newest pending
                        asm volatile("cp.async.bulk.wait_group.read 1;" ::: "memory");
                        int b2 = (i + 2) % NSLOT;
                        int rn = atomicAdd(&g_row_ctr, TILER);
                        rowbuf[b2] = rn;
                        if (rn < Nn) {
                            unsigned mbb = sbase + WB_MBAR + b2 * 8;
                            mbar_expect_tx_(mbb, TILEB);
                            bulk_g2s_(sbase + b2 * TILEB, W + (size_t)rn * Nn, TILEB, mbb);
                        }
                    }
                }
                __syncthreads();                   // rowbuf visible to all
            }
            if (tid == 0)
                asm volatile("cp.async.bulk.wait_group 0;" ::: "memory");
        }
        __syncthreads();
        if (tid == 0) { __threadfence(); atomicAdd(&g_gemv_done, 1); }
        return;
    }

    // ======================= scan CTA (bid == 0) =======================
    SS* sm = reinterpret_cast<SS*>(smraw);

    const int step = step_ptr ? *step_ptr : 1;
    const int mode = ((step % 3) + 3) % 3;

    if (tid < Kk) {
        sm->spp[tid]  = spark_pos[tid];
        sm->sen[tid]  = energy[tid];
        sm->srnd[tid] = randint_vals[tid];
    }
    if (tid == 0) sm->list_cnt = 0;
    for (int i = tid; i < Nn; i += 1024) { sm->row2b[i] = 255u; sm->rowT[i] = 0u; }
    for (int i = tid; i < HASHSZ; i += 1024) { sm->hkey[i] = 0xFFFFFFFFu; sm->hval[i] = 0.f; }
    __syncthreads();
    if (tid < Kk) sm->row2b[sm->spp[tid]] = (unsigned char)tid;
    if (tid == 0) {
        while (atomicAdd(&g_spark_done, 0) < Kk) __nanosleep(128);
    }
    __syncthreads();
    {
        unsigned long long* td = &sm->top[0][0];
        const unsigned long long* tsrc = &g_top[0][0];
        for (int i = tid; i < Kk * RR; i += 1024) td[i] = tsrc[i];
    }
    if (tid < Kk) sm->s_spark[tid] = g_sspark[tid];
    __syncthreads();
    if (tid < Kk && spark_age[tid] < 5) {
        int p = sm->spp[tid];
        if (p >= 0 && p < Nn) sm->s_spark[sm->row2b[p]] = 1.0f;
    }
    __syncthreads();

    if (wid == 0) {
        // upfront hebbian-base speculative prefetch (raw W values)
        if (mode != 2) {
            for (int it = 0; it < Kk; ++it) {
                int col = key_idx(sm->top[it][lane]);
                cp_async4(&sm->spec[it][lane], W + (size_t)col * Nn + sm->spp[it]);
            }
        } else {
            for (int it = lane; it < Kk; it += 32)
                cp_async4(&sm->specR[it], W + (size_t)sm->srnd[it] * Nn + sm->spp[it]);
        }
        asm volatile("cp.async.commit_group;" ::: "memory");
        asm volatile("cp.async.wait_group 0;" ::: "memory");

        // =============== serial loop (warp 0, hash-free) ===============
        for (int it = 0; it < Kk; ++it) {
            const int prev = sm->spp[it];
            const bool rowPconf = (sm->rowT[prev] != 0);
            const int nrecs = it * 36;

            unsigned long long t[6];
            if (!rowPconf) {
                #pragma unroll
                for (int q = 0; q < 6; ++q) t[q] = sm->top[it][q];
            } else {
                // SLOW PATH: gather this row's prior records (ordered scan)
                int mcnt = 0;
                for (int bj = 0; bj < nrecs; bj += 32) {
                    int j = bj + lane;
                    unsigned long long rc = (j < nrecs) ? sm->rec[j] : 0ull;
                    bool m = (j < nrecs) && ((unsigned)(rc >> 45) == (unsigned)prev);
                    unsigned bm = __ballot_sync(0xFFFFFFFFu, m);
                    int rk = __popc(bm & ((1u << lane) - 1));
                    if (m && (mcnt + rk) < 64) sm->scr[mcnt + rk] = rc;
                    mcnt += __popc(bm);
                }
                if (mcnt > 64) mcnt = 64;
                __syncwarp();

                int nchunk = (mcnt + 31) / 32;
                for (int ch = 0; ch < nchunk; ++ch) {
                    int idx = ch * 32 + lane;
                    bool act = idx < mcnt;
                    unsigned long long rc = act ? sm->scr[idx] : 0ull;
                    unsigned mykey = act ? (unsigned)(rc >> 32)
                                         : (0x80000000u | (unsigned)lane | ((unsigned)ch << 8));
                    unsigned grp = __match_any_sync(0xFFFFFFFFu, mykey);
                    bool leader = act && ((grp & ((1u << lane) - 1)) == 0);
                    if (leader)
                        for (int q = 0; q < ch * 32; ++q)
                            if ((unsigned)(sm->scr[q] >> 32) == mykey) { leader = false; break; }
                    unsigned long long cnd = 0ull;
                    if (leader) {
                        float dsum = 0.f;
                        for (int q = 0; q < mcnt; ++q) {
                            unsigned long long e = sm->scr[q];
                            if ((unsigned)(e >> 32) == mykey)
                                dsum += __uint_as_float((unsigned)e);
                        }
                        int col = (int)(mykey & (Nn - 1));
                        float bse; bool fnd = false;
                        for (int q = 0; q < RR; ++q) {
                            unsigned long long e = sm->top[it][q];
                            if (key_idx(e) == col) {
                                unsigned hk = (unsigned)(e >> 32);
                                if (hk > 1u) { bse = __uint_as_float(hk - 1u); fnd = true; }
                                break;
                            }
                        }
                        if (!fnd) bse = __ldg(&W[(size_t)prev * Nn + col]);
                        cnd = pack64(valkey(bse + dsum), col);
                    }
                    sm->scr2[ch * 32 + lane] = cnd;
                    __syncwarp();
                }
                for (int q = mcnt; q < 64; q += 32)
                    if (q + lane < 64 && q + lane >= mcnt) sm->scr2[q + lane] = 0ull;
                __syncwarp();

                unsigned long long mine[4];
                mine[0] = sm->top[it][lane];
                mine[1] = sm->top[it][lane + 32];
                mine[2] = sm->scr2[lane];
                mine[3] = sm->scr2[lane + 32];
                for (int q = 0; q < mcnt; ++q) {
                    int col = (int)((unsigned)(sm->scr[q] >> 32) & (Nn - 1));
                    if (key_idx(mine[0]) == col) mine[0] = 0ull;
                    if (key_idx(mine[1]) == col) mine[1] = 0ull;
                }
                #pragma unroll
                for (int pp = 0; pp < 6; ++pp) {
                    unsigned long long b = mine[0];
                    if (mine[1] > b) b = mine[1];
                    if (mine[2] > b) b = mine[2];
                    if (mine[3] > b) b = mine[3];
                    unsigned hi = (unsigned)(b >> 32);
                    unsigned himax = __reduce_max_sync(0xFFFFFFFFu, hi);
                    unsigned lo = (hi == himax) ? (unsigned)b : 0u;
                    unsigned lomax = __reduce_max_sync(0xFFFFFFFFu, lo);
                    unsigned long long win = ((unsigned long long)himax << 32) | lomax;
                    t[pp] = win;
                    #pragma unroll
                    for (int q = 0; q < 4; ++q) if (mine[q] == win) mine[q] = 0ull;
                }
            }

            const int next = (mode == 2) ? sm->srnd[it] : key_idx(t[0]);
            const bool rowNconf = (sm->rowT[next] != 0);

            float prior = 0.f;
            if (rowNconf) {
                unsigned hk = ((unsigned)next << 13) | (unsigned)prev;
                float ps = 0.f;
                for (int j = lane; j < nrecs; j += 32) {
                    unsigned long long rc = sm->rec[j];
                    if ((unsigned)(rc >> 32) == hk) ps += __uint_as_float((unsigned)rc);
                }
                #pragma unroll
                for (int off = 16; off; off >>= 1)
                    ps += __shfl_xor_sync(0xFFFFFFFFu, ps, off);
                prior = ps;
            }
            float base;
            if (mode == 2) {
                base = sm->specR[it];
            } else {
                int myc = key_idx(sm->top[it][lane]);
                unsigned mmask = __ballot_sync(0xFFFFFFFFu, myc == next);
                if (mmask) {
                    float bl = sm->spec[it][lane];
                    base = __shfl_sync(0xFFFFFFFFu, bl, __ffs(mmask) - 1);
                } else {
                    base = __ldg(&W[(size_t)next * Nn + prev]);
                }
            }
            const float cur  = base + prior;
            const float sp   = sm->s_spark[sm->row2b[prev]];
            const float hnew = cur * 0.95f + sp * 0.05f;

            unsigned long long top5[5];
            if (next == prev) {
                unsigned long long cnd[7];
                int cn = 0;
                #pragma unroll
                for (int q = 0; q < 6; ++q)
                    if (key_idx(t[q]) != prev) cnd[cn++] = t[q];
                cnd[cn++] = pack64(valkey(hnew), prev);
                for (int a = 1; a < cn; ++a) {
                    unsigned long long kx = cnd[a];
                    int b = a - 1;
                    while (b >= 0 && cnd[b] < kx) { cnd[b + 1] = cnd[b]; --b; }
                    cnd[b + 1] = kx;
                }
                #pragma unroll
                for (int q = 0; q < 5; ++q) top5[q] = cnd[q];
            } else {
                #pragma unroll
                for (int q = 0; q < 5; ++q) top5[q] = t[q];
            }
            int t5r[5];
            #pragma unroll
            for (int q = 0; q < 5; ++q) t5r[q] = key_idx(top5[q]);

            for (int u = lane; u < 35; u += 32) {
                int r, c; float d;
                if (u < 5)       { r = prev;       c = t5r[u];   d = 0.01f;  }
                else if (u < 10) { r = t5r[u - 5]; c = prev;     d = 0.005f; }
                else { int a2 = (u - 10) / 5, b2 = (u - 10) % 5;
                       r = t5r[a2]; c = t5r[b2];   d = 0.003f; }
                unsigned key = ((unsigned)r << 13) | (unsigned)c;
                sm->rec[nrecs + u] = ((unsigned long long)key << 32) | __float_as_uint(d);
            }
            if (lane == 0) {
                unsigned key = ((unsigned)next << 13) | (unsigned)prev;
                sm->rec[nrecs + 35] =
                    ((unsigned long long)key << 32) | __float_as_uint(hnew - cur);
                sm->next_all[it] = next;
                unsigned bn = sm->row2b[next];
                if (bn != 255u) sm->s_spark[bn] = sm->sen[it] * 0.98f;
            }
            if (lane == 0)               sm->rowT[prev] = 1u;
            if (lane >= 1 && lane <= 5)  sm->rowT[t5r[lane - 1]] = 1u;
            if (lane == 6)               sm->rowT[next] = 1u;
            __syncwarp();
        }
    }
    __syncthreads();

    // ---- parallel accumulation of records ----
    for (int i = tid; i < NREC; i += 1024) {
        unsigned long long rc = sm->rec[i];
        hadd_ep(sm, (unsigned)(rc >> 32), __uint_as_float((unsigned)rc));
    }
    __syncthreads();

    // ---- epilogue part 1: pos/energy/age ----
    if (tid < Kk) {
        float ed   = sm->sen[tid] * 0.98f;
        bool reset = ed < 0.05f;
        int pn = reset ? (tid % Nn) : sm->next_all[tid];
        out[tid]      = (float)pn;
        out[oE + tid] = reset ? 1.0f : ed;
        out[oA + tid] = (float)(reset ? 0 : (spark_age[tid] + 1));
    }

    if (tid == 0) {
        while (atomicAdd(&g_gemv_done, 0) < NWORK) __nanosleep(128);
    }
    __syncthreads();

    if (tid == 0) {
        for (int b = 0; b < Kk; ++b)
            if (spark_age[b] < 5) {
                int p = sm->spp[b];
                if (p >= 0 && p < Nn) out[oS + p] = 1.0f;
            }
        for (int it = 0; it < Kk; ++it)
            out[oS + sm->next_all[it]] = sm->sen[it] * 0.98f;
    }
    {
        int nl = sm->list_cnt;
        for (int j = tid; j < nl; j += 1024) {
            unsigned slot = sm->list[j];
            unsigned key  = sm->hkey[slot];
            int r = (int)(key >> 13), c = (int)(key & (Nn - 1));
            float b = __ldg(&W[(size_t)r * Nn + c]);
            float v = (b + sm->hval[slot]) * 0.999f;
            out[oW + (size_t)r * Nn + c] = fminf(fmaxf(v, -2.f), 2.f);
        }
    }
    __syncthreads();
    if (tid == 0) {                       // replay determinism
        g_spark_done = 0; g_gemv_done = 0; g_row_ctr = 0;
    }
}

// ---------------------------------------------------------------------------
// launch
// ---------------------------------------------------------------------------
extern "C" void kernel_launch(void* const* d_in, const int* in_sizes, int n_in,
                              void* d_out, int out_size)
{
    const float* W      = (const float*)d_in[0];
    const float* s      = (const float*)d_in[1];
    const float* noise  = (const float*)d_in[2];
    // d_in[3] = unif : unused (scalar gumbel shift doesn't change argmax)
    const float* energy = (const float*)d_in[4];
    const int* spark_pos = (const int*)d_in[5];
    const int* spark_age = (const int*)d_in[6];
    const int* randint   = (const int*)d_in[7];
    const int* step      = (n_in > 8) ? (const int*)d_in[8] : nullptr;
    float* out = (float*)d_out;

    (void)in_sizes; (void)out_size;

    static_assert(sizeof(SS) <= SMEMSZ, "scan view must fit worker allocation");
    cudaFuncSetAttribute(fused_kernel, cudaFuncAttributeMaxDynamicSharedMemorySize,
                         SMEMSZ);
    fused_kernel<<<GRIDSZ, 1024, SMEMSZ>>>(W, s, noise, energy, spark_pos,
                                           spark_age, randint, step, out);
}

// round 17
// speedup vs baseline: 1.1709x; 1.1709x over previous
#include <cuda_runtime.h>
#include <cstdint>
#include <cstddef>

#define Nn 8192
#define Kk 64
#define RR 64                  // base top-R per spark row (sorted desc)
#define HASHSZ 4096
#define LISTCAP 2432
#define NREC (Kk * 36)
#define NWORK 147              // worker CTAs (stream pool)
#define GRIDSZ (1 + NWORK)
#define ROWB 32768             // 32KB row
#define NSLOT 3                // ring slots (2 rows in flight) — R14 optimum
// worker view of dynamic smem: NSLOT row buffers + mbars + rowbuf
#define WB_MBAR (NSLOT * ROWB)            // 98304
#define WB_ROWS (WB_MBAR + NSLOT * 8)

// ---------------------------------------------------------------------------
// device globals (counters reset at end of each run for graph replay)
// ---------------------------------------------------------------------------
__device__ unsigned long long g_top[Kk][RR];
__device__ float g_sspark[Kk];
__device__ int g_spark_done;
__device__ int g_gemv_done;
__device__ int g_row_ctr;

__device__ __forceinline__ unsigned valkey(float v) {
    return ((v > 0.f) ? __float_as_uint(v) : 0u) + 1u;
}
__device__ __forceinline__ unsigned long long pack64(unsigned key, int col) {
    return ((unsigned long long)key << 32) | (unsigned)(~(unsigned)col);
}
__device__ __forceinline__ int key_idx(unsigned long long k) {
    return (int)(~(unsigned)k);
}
__device__ __forceinline__ unsigned hash_h(unsigned key) {
    return (key * 2654435761u) & (HASHSZ - 1);
}
__device__ __forceinline__ unsigned smem_u32(const void* p) {
    return (unsigned)__cvta_generic_to_shared(p);
}
__device__ __forceinline__ void cp_async4(void* smem_dst, const void* gptr) {
    unsigned a = smem_u32(smem_dst);
    asm volatile("cp.async.ca.shared.global [%0], [%1], 4;" :: "r"(a), "l"(gptr) : "memory");
}
__device__ __forceinline__ void mbar_init_(unsigned a, unsigned cnt) {
    asm volatile("mbarrier.init.shared.b64 [%0], %1;" :: "r"(a), "r"(cnt) : "memory");
}
__device__ __forceinline__ void mbar_expect_tx_(unsigned a, unsigned bytes) {
    asm volatile("mbarrier.arrive.expect_tx.shared.b64 _, [%0], %1;" :: "r"(a), "r"(bytes) : "memory");
}
__device__ __forceinline__ void mbar_wait_(unsigned a, unsigned parity) {
    asm volatile(
        "{\n\t.reg .pred P;\n"
        "LWAIT%=:\n\t"
        "mbarrier.try_wait.parity.shared.b64 P, [%0], %1;\n\t"
        "@!P bra LWAIT%=;\n\t}"
        :: "r"(a), "r"(parity) : "memory");
}
__device__ __forceinline__ void bulk_g2s_(unsigned dst, const void* src, unsigned bytes, unsigned mbar) {
    asm volatile(
        "cp.async.bulk.shared::cluster.global.mbarrier::complete_tx::bytes [%0], [%1], %2, [%3];"
        :: "r"(dst), "l"(src), "r"(bytes), "r"(mbar) : "memory");
}
__device__ __forceinline__ void bulk_s2g_(void* gdst, unsigned ssrc, unsigned bytes) {
    asm volatile(
        "cp.async.bulk.global.shared::cta.bulk_group [%0], [%1], %2;"
        :: "l"(gdst), "r"(ssrc), "r"(bytes) : "memory");
}

// ---------------------------------------------------------------------------
// Scan shared memory (scan CTA view of the dynamic smem)
// ---------------------------------------------------------------------------
struct alignas(16) SS {
    unsigned long long top[Kk][RR];       // 32KB sorted base top lists
    unsigned long long rec[NREC];         // 18KB ordered additive records
    unsigned char rowT[Nn];               // 8KB  row-touched map
    unsigned hkey[HASHSZ];                // 16KB (epilogue accumulation)
    float    hval[HASHSZ];                // 16KB
    unsigned list[LISTCAP];               // 9.5KB distinct elements
    unsigned long long scr[64];
    unsigned long long scr2[64];
    float spec[Kk][32];                   // upfront hebbian-base prefetch
    float specR[Kk];
    float s_spark[Kk];
    unsigned char row2b[Nn];              // 8KB row -> spark bucket (255=none)
    int   spp[Kk]; float sen[Kk]; int srnd[Kk];
    int   next_all[Kk];
    int   list_cnt;
};

// epilogue-only atomic accumulate (parallel, commutative adds)
__device__ void hadd_ep(SS* sm, unsigned key, float d) {
    unsigned h = hash_h(key);
    while (true) {
        unsigned k = sm->hkey[h];
        if (k == 0xFFFFFFFFu) {
            unsigned old = atomicCAS(&sm->hkey[h], 0xFFFFFFFFu, key);
            if (old == 0xFFFFFFFFu) {
                atomicAdd(&sm->hval[h], d);
                int li = atomicAdd(&sm->list_cnt, 1);
                sm->list[li] = h;
                return;
            }
            k = old;
        }
        if (k == key) { atomicAdd(&sm->hval[h], d); return; }
        h = (h + 1) & (HASHSZ - 1);
    }
}

// ---------------------------------------------------------------------------
// ONE fused kernel, one wave (148 CTAs):
//   CTA 0        : sequential spark scan (record-based, hash-free loop)
//   CTA 1..64    : spark row top-64 + sigmoid, then join bulk-stream queue
//   CTA 65..147  : bulk-stream queue immediately (3-slot TMA ring; warp 1
//                  owns the TMA chain, warp 0 the sigmoid — overlapped)
// ---------------------------------------------------------------------------
__global__ void __launch_bounds__(1024, 1) fused_kernel(
    const float* __restrict__ W,
    const float* __restrict__ s_in,
    const float* __restrict__ noise,
    const float* __restrict__ energy,
    const int*   __restrict__ spark_pos,
    const int*   __restrict__ spark_age,
    const int*   __restrict__ randint_vals,
    const int*   __restrict__ step_ptr,
    float*       __restrict__ out)
{
    __shared__ unsigned long long wl[32][RR];
    __shared__ float red[32];

    extern __shared__ unsigned char smraw[];

    const int tid  = threadIdx.x;
    const int lane = tid & 31;
    const int wid  = tid >> 5;
    const int bid  = blockIdx.x;

    const size_t oS = Kk;
    const size_t oW = (size_t)Kk + Nn;
    const size_t oE = oW + (size_t)Nn * Nn;
    const size_t oA = oE + Kk;

    // ======================= worker CTAs =======================
    if (bid >= 1) {
        unsigned sbase = smem_u32(smraw);
        float4* fbuf = reinterpret_cast<float4*>(smraw);
        int* rowbuf  = reinterpret_cast<int*>(smraw + WB_ROWS);

        if (tid == 0) {
            #pragma unroll
            for (int q = 0; q < NSLOT; ++q)
                mbar_init_(sbase + WB_MBAR + q * 8, 1);
            asm volatile("fence.proxy.async.shared::cta;" ::: "memory");
        }
        __syncthreads();

        // ---- spark prep (CTAs 1..Kk only) ----
        if (bid <= Kk) {
            const int b   = bid - 1;
            const int row = spark_pos[b];
            const float4* r4 = reinterpret_cast<const float4*>(W + (size_t)row * Nn);
            {
                const int cbase = (wid << 8) + (lane << 3);
                float4 a = __ldg(&r4[cbase >> 2]);
                float4 c = __ldg(&r4[(cbase >> 2) + 1]);
                unsigned k0 = valkey(a.x), k1 = valkey(a.y), k2 = valkey(a.z), k3 = valkey(a.w);
                unsigned k4 = valkey(c.x), k5 = valkey(c.y), k6 = valkey(c.z), k7 = valkey(c.w);
                for (int p = 0; p < RR; ++p) {
                    unsigned bk = k0; int bj = 0;
                    if (k1 > bk) { bk = k1; bj = 1; }
                    if (k2 > bk) { bk = k2; bj = 2; }
                    if (k3 > bk) { bk = k3; bj = 3; }
                    if (k4 > bk) { bk = k4; bj = 4; }
                    if (k5 > bk) { bk = k5; bj = 5; }
                    if (k6 > bk) { bk = k6; bj = 6; }
                    if (k7 > bk) { bk = k7; bj = 7; }
                    unsigned kmax = __reduce_max_sync(0xFFFFFFFFu, bk);
                    unsigned cnd = (bk == kmax) ? (unsigned)(cbase + bj) : 0xFFFFFFFFu;
                    unsigned cmin = __reduce_min_sync(0xFFFFFFFFu, cnd);
                    if (lane == 0) wl[wid][p] = pack64(kmax, (int)cmin);
                    int rel = (int)cmin - cbase;
                    if (rel >= 0 && rel < 8) {
                        if (rel == 0) k0 = 0; if (rel == 1) k1 = 0;
                        if (rel == 2) k2 = 0; if (rel == 3) k3 = 0;
                        if (rel == 4) k4 = 0; if (rel == 5) k5 = 0;
                        if (rel == 6) k6 = 0; if (rel == 7) k7 = 0;
                    }
                }
                __syncthreads();
                if (wid == 0) {
                    int head = 0;
                    for (int p = 0; p < RR; ++p) {
                        unsigned long long cur = (head < RR) ? wl[lane][head] : 0ull;
                        unsigned hi = (unsigned)(cur >> 32);
                        unsigned kmax = __reduce_max_sync(0xFFFFFFFFu, hi);
                        unsigned lo = (hi == kmax) ? (unsigned)cur : 0u;
                        unsigned lomax = __reduce_max_sync(0xFFFFFFFFu, lo);
                        if (hi == kmax && (unsigned)cur == lomax) head++;
                        if (lane == 0)
                            g_top[b][p] = ((unsigned long long)kmax << 32) | lomax;
                    }
                }
            }
            {
                const float4* s4 = reinterpret_cast<const float4*>(s_in);
                float4 w1 = __ldg(&r4[2 * tid]),     w2 = __ldg(&r4[2 * tid + 1]);
                float4 v1 = __ldg(&s4[2 * tid]),     v2 = __ldg(&s4[2 * tid + 1]);
                float acc = w1.x * (v1.x * 0.95f) + w1.y * (v1.y * 0.95f)
                          + w1.z * (v1.z * 0.95f) + w1.w * (v1.w * 0.95f)
                          + w2.x * (v2.x * 0.95f) + w2.y * (v2.y * 0.95f)
                          + w2.z * (v2.z * 0.95f) + w2.w * (v2.w * 0.95f);
                #pragma unroll
                for (int off = 16; off; off >>= 1)
                    acc += __shfl_xor_sync(0xFFFFFFFFu, acc, off);
                if (lane == 0) red[wid] = acc;
                __syncthreads();
                if (wid == 0) {
                    float v = red[lane];
                    #pragma unroll
                    for (int off = 16; off; off >>= 1)
                        v += __shfl_xor_sync(0xFFFFFFFFu, v, off);
                    if (lane == 0) {
                        float z = v + 0.05f * noise[row];
                        g_sspark[b] = 1.0f / (1.0f + expf(-z));
                        __threadfence();
                        atomicAdd(&g_spark_done, 1);
                    }
                }
            }
            __syncthreads();
        }

        // ---- bulk-stream queue: 3-slot TMA ring, split-warp bookkeeping ----
        {
            const float4* s4 = reinterpret_cast<const float4*>(s_in);
            float4 sv0 = __ldg(&s4[2 * tid]);
            float4 sv1 = __ldg(&s4[2 * tid + 1]);
            sv0.x *= 0.95f; sv0.y *= 0.95f; sv0.z *= 0.95f; sv0.w *= 0.95f;
            sv1.x *= 0.95f; sv1.y *= 0.95f; sv1.z *= 0.95f; sv1.w *= 0.95f;

            // prologue: grab two rows, issue loads into slots 0..1
            if (tid == 0) {
                #pragma unroll
                for (int q = 0; q < 2; ++q) {
                    int r0 = atomicAdd(&g_row_ctr, 1);
                    rowbuf[q] = r0;
                    if (r0 < Nn) {
                        mbar_expect_tx_(sbase + WB_MBAR + q * 8, ROWB);
                        bulk_g2s_(sbase + q * ROWB, W + (size_t)r0 * Nn, ROWB,
                                  sbase + WB_MBAR + q * 8);
                    }
                }
                rowbuf[2] = Nn + 1;
            }
            __syncthreads();

            for (int i = 0;; ++i) {
                const int a = i % NSLOT;
                const int row = rowbuf[a];
                if (row >= Nn) break;

                float nz = 0.f;
                if (tid == 0) nz = __ldg(&noise[row]);   // overlaps mbar wait

                mbar_wait_(sbase + WB_MBAR + a * 8, (unsigned)((i / NSLOT) & 1));

                float4* bp = fbuf + a * 2048;
                float4 w1 = bp[2 * tid];
                float4 w2 = bp[2 * tid + 1];
                float acc = w1.x * sv0.x + w1.y * sv0.y + w1.z * sv0.z + w1.w * sv0.w
                          + w2.x * sv1.x + w2.y * sv1.y + w2.z * sv1.z + w2.w * sv1.w;
                float4 o1, o2;
                o1.x = fminf(fmaxf(w1.x * 0.999f, -2.f), 2.f);
                o1.y = fminf(fmaxf(w1.y * 0.999f, -2.f), 2.f);
                o1.z = fminf(fmaxf(w1.z * 0.999f, -2.f), 2.f);
                o1.w = fminf(fmaxf(w1.w * 0.999f, -2.f), 2.f);
                o2.x = fminf(fmaxf(w2.x * 0.999f, -2.f), 2.f);
                o2.y = fminf(fmaxf(w2.y * 0.999f, -2.f), 2.f);
                o2.z = fminf(fmaxf(w2.z * 0.999f, -2.f), 2.f);
                o2.w = fminf(fmaxf(w2.w * 0.999f, -2.f), 2.f);
                bp[2 * tid]     = o1;
                bp[2 * tid + 1] = o2;

                #pragma unroll
                for (int off = 16; off; off >>= 1)
                    acc += __shfl_xor_sync(0xFFFFFFFFu, acc, off);
                if (lane == 0) red[wid] = acc;
                __syncthreads();      // single barrier: smem clip + red ready

                if (wid == 1 && lane == 0) {
                    // TMA chain (runs concurrently with warp 0's reduction)
                    asm volatile("fence.proxy.async.shared::cta;" ::: "memory");
                    bulk_s2g_(out + oW + (size_t)row * Nn, sbase + a * ROWB, ROWB);
                    asm volatile("cp.async.bulk.commit_group;" ::: "memory");
                    // slot (i+2)%3 was stored at iter i-1; allow 1 newest pending
                    asm volatile("cp.async.bulk.wait_group.read 1;" ::: "memory");
                    int b2 = (i + 2) % NSLOT;
                    int rn = atomicAdd(&g_row_ctr, 1);
                    rowbuf[b2] = rn;            // read at iter i+2, ordered by
                    if (rn < Nn) {              // the mid barrier of iter i+1
                        unsigned mbb = sbase + WB_MBAR + b2 * 8;
                        mbar_expect_tx_(mbb, ROWB);
                        bulk_g2s_(sbase + b2 * ROWB, W + (size_t)rn * Nn, ROWB, mbb);
                    }
                }
                if (wid == 0) {
                    float v = red[lane];
                    #pragma unroll
                    for (int off = 16; off; off >>= 1)
                        v += __shfl_xor_sync(0xFFFFFFFFu, v, off);
                    if (lane == 0) {
                        float z = v + 0.05f * nz;
                        out[oS + row] = 1.0f / (1.0f + expf(-z));
                    }
                }
                // no trailing barrier: next iteration's mid barrier orders
                // rowbuf/slot reuse (written at i, read at i+2)
            }
            if (tid == 32)   // warp 1 lane 0 owns the bulk-store groups
                asm volatile("cp.async.bulk.wait_group 0;" ::: "memory");
        }
        __syncthreads();
        if (tid == 0) { __threadfence(); atomicAdd(&g_gemv_done, 1); }
        return;
    }

    // ======================= scan CTA (bid == 0) =======================
    SS* sm = reinterpret_cast<SS*>(smraw);

    const int step = step_ptr ? *step_ptr : 1;
    const int mode = ((step % 3) + 3) % 3;

    if (tid < Kk) {
        sm->spp[tid]  = spark_pos[tid];
        sm->sen[tid]  = energy[tid];
        sm->srnd[tid] = randint_vals[tid];
    }
    if (tid == 0) sm->list_cnt = 0;
    for (int i = tid; i < Nn; i += 1024) { sm->row2b[i] = 255u; sm->rowT[i] = 0u; }
    for (int i = tid; i < HASHSZ; i += 1024) { sm->hkey[i] = 0xFFFFFFFFu; sm->hval[i] = 0.f; }
    __syncthreads();
    if (tid < Kk) sm->row2b[sm->spp[tid]] = (unsigned char)tid;
    if (tid == 0) {
        while (atomicAdd(&g_spark_done, 0) < Kk) __nanosleep(128);
    }
    __syncthreads();
    {
        unsigned long long* td = &sm->top[0][0];
        const unsigned long long* tsrc = &g_top[0][0];
        for (int i = tid; i < Kk * RR; i += 1024) td[i] = tsrc[i];
    }
    if (tid < Kk) sm->s_spark[tid] = g_sspark[tid];
    __syncthreads();
    if (tid < Kk && spark_age[tid] < 5) {
        int p = sm->spp[tid];
        if (p >= 0 && p < Nn) sm->s_spark[sm->row2b[p]] = 1.0f;
    }
    __syncthreads();

    if (wid == 0) {
        // upfront hebbian-base speculative prefetch (raw W values)
        if (mode != 2) {
            for (int it = 0; it < Kk; ++it) {
                int col = key_idx(sm->top[it][lane]);
                cp_async4(&sm->spec[it][lane], W + (size_t)col * Nn + sm->spp[it]);
            }
        } else {
            for (int it = lane; it < Kk; it += 32)
                cp_async4(&sm->specR[it], W + (size_t)sm->srnd[it] * Nn + sm->spp[it]);
        }
        asm volatile("cp.async.commit_group;" ::: "memory");
        asm volatile("cp.async.wait_group 0;" ::: "memory");

        // =============== serial loop (warp 0, hash-free) ===============
        for (int it = 0; it < Kk; ++it) {
            const int prev = sm->spp[it];
            const bool rowPconf = (sm->rowT[prev] != 0);
            const int nrecs = it * 36;

            unsigned long long t[6];
            if (!rowPconf) {
                #pragma unroll
                for (int q = 0; q < 6; ++q) t[q] = sm->top[it][q];
            } else {
                // SLOW PATH: gather this row's prior records (ordered scan)
                int mcnt = 0;
                for (int bj = 0; bj < nrecs; bj += 32) {
                    int j = bj + lane;
                    unsigned long long rc = (j < nrecs) ? sm->rec[j] : 0ull;
                    bool m = (j < nrecs) && ((unsigned)(rc >> 45) == (unsigned)prev);
                    unsigned bm = __ballot_sync(0xFFFFFFFFu, m);
                    int rk = __popc(bm & ((1u << lane) - 1));
                    if (m && (mcnt + rk) < 64) sm->scr[mcnt + rk] = rc;
                    mcnt += __popc(bm);
                }
                if (mcnt > 64) mcnt = 64;
                __syncwarp();

                int nchunk = (mcnt + 31) / 32;
                for (int ch = 0; ch < nchunk; ++ch) {
                    int idx = ch * 32 + lane;
                    bool act = idx < mcnt;
                    unsigned long long rc = act ? sm->scr[idx] : 0ull;
                    unsigned mykey = act ? (unsigned)(rc >> 32)
                                         : (0x80000000u | (unsigned)lane | ((unsigned)ch << 8));
                    unsigned grp = __match_any_sync(0xFFFFFFFFu, mykey);
                    bool leader = act && ((grp & ((1u << lane) - 1)) == 0);
                    if (leader)
                        for (int q = 0; q < ch * 32; ++q)
                            if ((unsigned)(sm->scr[q] >> 32) == mykey) { leader = false; break; }
                    unsigned long long cnd = 0ull;
                    if (leader) {
                        float dsum = 0.f;
                        for (int q = 0; q < mcnt; ++q) {
                            unsigned long long e = sm->scr[q];
                            if ((unsigned)(e >> 32) == mykey)
                                dsum += __uint_as_float((unsigned)e);
                        }
                        int col = (int)(mykey & (Nn - 1));
                        float bse; bool fnd = false;
                        for (int q = 0; q < RR; ++q) {
                            unsigned long long e = sm->top[it][q];
                            if (key_idx(e) == col) {
                                unsigned hk = (unsigned)(e >> 32);
                                if (hk > 1u) { bse = __uint_as_float(hk - 1u); fnd = true; }
                                break;
                            }
                        }
                        if (!fnd) bse = __ldg(&W[(size_t)prev * Nn + col]);
                        cnd = pack64(valkey(bse + dsum), col);
                    }
                    sm->scr2[ch * 32 + lane] = cnd;
                    __syncwarp();
                }
                for (int q = mcnt; q < 64; q += 32)
                    if (q + lane < 64 && q + lane >= mcnt) sm->scr2[q + lane] = 0ull;
                __syncwarp();

                unsigned long long mine[4];
                mine[0] = sm->top[it][lane];
                mine[1] = sm->top[it][lane + 32];
                mine[2] = sm->scr2[lane];
                mine[3] = sm->scr2[lane + 32];
                for (int q = 0; q < mcnt; ++q) {
                    int col = (int)((unsigned)(sm->scr[q] >> 32) & (Nn - 1));
                    if (key_idx(mine[0]) == col) mine[0] = 0ull;
                    if (key_idx(mine[1]) == col) mine[1] = 0ull;
                }
                #pragma unroll
                for (int pp = 0; pp < 6; ++pp) {
                    unsigned long long b = mine[0];
                    if (mine[1] > b) b = mine[1];
                    if (mine[2] > b) b = mine[2];
                    if (mine[3] > b) b = mine[3];
                    unsigned hi = (unsigned)(b >> 32);
                    unsigned himax = __reduce_max_sync(0xFFFFFFFFu, hi);
                    unsigned lo = (hi == himax) ? (unsigned)b : 0u;
                    unsigned lomax = __reduce_max_sync(0xFFFFFFFFu, lo);
                    unsigned long long win = ((unsigned long long)himax << 32) | lomax;
                    t[pp] = win;
                    #pragma unroll
                    for (int q = 0; q < 4; ++q) if (mine[q] == win) mine[q] = 0ull;
                }
            }

            const int next = (mode == 2) ? sm->srnd[it] : key_idx(t[0]);
            const bool rowNconf = (sm->rowT[next] != 0);

            float prior = 0.f;
            if (rowNconf) {
                unsigned hk = ((unsigned)next << 13) | (unsigned)prev;
                float ps = 0.f;
                for (int j = lane; j < nrecs; j += 32) {
                    unsigned long long rc = sm->rec[j];
                    if ((unsigned)(rc >> 32) == hk) ps += __uint_as_float((unsigned)rc);
                }
                #pragma unroll
                for (int off = 16; off; off >>= 1)
                    ps += __shfl_xor_sync(0xFFFFFFFFu, ps, off);
                prior = ps;
            }
            float base;
            if (mode == 2) {
                base = sm->specR[it];
            } else {
                int myc = key_idx(sm->top[it][lane]);
                unsigned mmask = __ballot_sync(0xFFFFFFFFu, myc == next);
                if (mmask) {
                    float bl = sm->spec[it][lane];
                    base = __shfl_sync(0xFFFFFFFFu, bl, __ffs(mmask) - 1);
                } else {
                    base = __ldg(&W[(size_t)next * Nn + prev]);
                }
            }
            const float cur  = base + prior;
            const float sp   = sm->s_spark[sm->row2b[prev]];
            const float hnew = cur * 0.95f + sp * 0.05f;

            unsigned long long top5[5];
            if (next == prev) {
                unsigned long long cnd[7];
                int cn = 0;
                #pragma unroll
                for (int q = 0; q < 6; ++q)
                    if (key_idx(t[q]) != prev) cnd[cn++] = t[q];
                cnd[cn++] = pack64(valkey(hnew), prev);
                for (int a = 1; a < cn; ++a) {
                    unsigned long long kx = cnd[a];
                    int b = a - 1;
                    while (b >= 0 && cnd[b] < kx) { cnd[b + 1] = cnd[b]; --b; }
                    cnd[b + 1] = kx;
                }
                #pragma unroll
                for (int q = 0; q < 5; ++q) top5[q] = cnd[q];
            } else {
                #pragma unroll
                for (int q = 0; q < 5; ++q) top5[q] = t[q];
            }
            int t5r[5];
            #pragma unroll
            for (int q = 0; q < 5; ++q) t5r[q] = key_idx(top5[q]);

            for (int u = lane; u < 35; u += 32) {
                int r, c; float d;
                if (u < 5)       { r = prev;       c = t5r[u];   d = 0.01f;  }
                else if (u < 10) { r = t5r[u - 5]; c = prev;     d = 0.005f; }
                else { int a2 = (u - 10) / 5, b2 = (u - 10) % 5;
                       r = t5r[a2]; c = t5r[b2];   d = 0.003f; }
                unsigned key = ((unsigned)r << 13) | (unsigned)c;
                sm->rec[nrecs + u] = ((unsigned long long)key << 32) | __float_as_uint(d);
            }
            if (lane == 0) {
                unsigned key = ((unsigned)next << 13) | (unsigned)prev;
                sm->rec[nrecs + 35] =
                    ((unsigned long long)key << 32) | __float_as_uint(hnew - cur);
                sm->next_all[it] = next;
                unsigned bn = sm->row2b[next];
                if (bn != 255u) sm->s_spark[bn] = sm->sen[it] * 0.98f;
            }
            if (lane == 0)               sm->rowT[prev] = 1u;
            if (lane >= 1 && lane <= 5)  sm->rowT[t5r[lane - 1]] = 1u;
            if (lane == 6)               sm->rowT[next] = 1u;
            __syncwarp();
        }
    }
    __syncthreads();

    // ---- parallel accumulation of records ----
    for (int i = tid; i < NREC; i += 1024) {
        unsigned long long rc = sm->rec[i];
        hadd_ep(sm, (unsigned)(rc >> 32), __uint_as_float((unsigned)rc));
    }
    __syncthreads();

    // ---- epilogue part 1: pos/energy/age ----
    if (tid < Kk) {
        float ed   = sm->sen[tid] * 0.98f;
        bool reset = ed < 0.05f;
        int pn = reset ? (tid % Nn) : sm->next_all[tid];
        out[tid]      = (float)pn;
        out[oE + tid] = reset ? 1.0f : ed;
        out[oA + tid] = (float)(reset ? 0 : (spark_age[tid] + 1));
    }

    if (tid == 0) {
        while (atomicAdd(&g_gemv_done, 0) < NWORK) __nanosleep(128);
    }
    __syncthreads();

    if (tid == 0) {
        for (int b = 0; b < Kk; ++b)
            if (spark_age[b] < 5) {
                int p = sm->spp[b];
                if (p >= 0 && p < Nn) out[oS + p] = 1.0f;
            }
        for (int it = 0; it < Kk; ++it)
            out[oS + sm->next_all[it]] = sm->sen[it] * 0.98f;
    }
    {
        int nl = sm->list_cnt;
        for (int j = tid; j < nl; j += 1024) {
            unsigned slot = sm->list[j];
            unsigned key  = sm->hkey[slot];
            int r = (int)(key >> 13), c = (int)(key & (Nn - 1));
            float b = __ldg(&W[(size_t)r * Nn + c]);
            float v = (b + sm->hval[slot]) * 0.999f;
            out[oW + (size_t)r * Nn + c] = fminf(fmaxf(v, -2.f), 2.f);
        }
    }
    __syncthreads();
    if (tid == 0) {                       // replay determinism
        g_spark_done = 0; g_gemv_done = 0; g_row_ctr = 0;
    }
}

// ---------------------------------------------------------------------------
// launch
// ---------------------------------------------------------------------------
extern "C" void kernel_launch(void* const* d_in, const int* in_sizes, int n_in,
                              void* d_out, int out_size)
{
    const float* W      = (const float*)d_in[0];
    const float* s      = (const float*)d_in[1];
    const float* noise  = (const float*)d_in[2];
    // d_in[3] = unif : unused (scalar gumbel shift doesn't change argmax)
    const float* energy = (const float*)d_in[4];
    const int* spark_pos = (const int*)d_in[5];
    const int* spark_age = (const int*)d_in[6];
    const int* randint   = (const int*)d_in[7];
    const int* step      = (n_in > 8) ? (const int*)d_in[8] : nullptr;
    float* out = (float*)d_out;

    (void)in_sizes; (void)out_size;

    static_assert(sizeof(SS) >= WB_ROWS + 64, "worker view must fit scan allocation");
    cudaFuncSetAttribute(fused_kernel, cudaFuncAttributeMaxDynamicSharedMemorySize,
                         (int)sizeof(SS));
    fused_kernel<<<GRIDSZ, 1024, sizeof(SS)>>>(W, s, noise, energy, spark_pos,
                                               spark_age, randint, step, out);
}